// round 1
// baseline (speedup 1.0000x reference)
#include <cuda_runtime.h>
#include <math.h>

#define TOK   2048
#define DDIM  1024
#define NEXP  15
#define KTOP  3
#define FF    1024
#define FSH   2048
#define NPAIR (TOK*KTOP)   // 6144

// ---------------- static scratch (no allocations allowed) ----------------
__device__ __align__(16) float g_h [(size_t)NPAIR * 2 * FF];   // expert fc1 out
__device__ __align__(16) float g_a [(size_t)NPAIR * FF];       // expert geglu out
__device__ __align__(16) float g_yp[(size_t)NPAIR * DDIM];     // expert fc2 out (per pair)
__device__ __align__(16) float g_hs[(size_t)TOK * 2 * FSH];    // shared fc1 out
__device__ __align__(16) float g_as[(size_t)TOK * FSH];        // shared geglu out
__device__ int   g_ptok[NPAIR];
__device__ int   g_pexp[NPAIR];
__device__ int   g_t2s [TOK * KTOP];
__device__ float g_tw  [TOK * KTOP];
__device__ int   g_ti  [TOK * KTOP];
__device__ int   g_cnt[NEXP], g_off[NEXP], g_cur[NEXP];

__device__ __forceinline__ float gelu_exact(float v) {
    return 0.5f * v * (1.0f + erff(v * 0.70710678118654752440f));
}

// ---------------- gating: logits -> softmax -> top3 -> counts ----------------
__global__ void zero_kernel() {
    int i = threadIdx.x;
    if (i < NEXP) g_cnt[i] = 0;
}

__global__ void gate_kernel(const float* __restrict__ x, const float* __restrict__ gw) {
    int t = blockIdx.x;
    int tid = threadIdx.x;   // 128 threads
    float part[NEXP];
#pragma unroll
    for (int e = 0; e < NEXP; e++) part[e] = 0.f;
    const float* xr = x + (size_t)t * DDIM;
    for (int d = tid; d < DDIM; d += 128) {
        float xv = xr[d];
#pragma unroll
        for (int e = 0; e < NEXP; e++) part[e] += xv * gw[e * DDIM + d];
    }
#pragma unroll
    for (int e = 0; e < NEXP; e++)
#pragma unroll
        for (int o = 16; o > 0; o >>= 1)
            part[e] += __shfl_xor_sync(0xFFFFFFFFu, part[e], o);

    __shared__ float red[NEXP][4];
    int w = tid >> 5, l = tid & 31;
    if (l == 0)
#pragma unroll
        for (int e = 0; e < NEXP; e++) red[e][w] = part[e];
    __syncthreads();

    if (tid == 0) {
        float lg[NEXP];
#pragma unroll
        for (int e = 0; e < NEXP; e++)
            lg[e] = red[e][0] + red[e][1] + red[e][2] + red[e][3];
        float mx = lg[0];
#pragma unroll
        for (int e = 1; e < NEXP; e++) mx = fmaxf(mx, lg[e]);
        float s = 0.f, sc[NEXP];
#pragma unroll
        for (int e = 0; e < NEXP; e++) { sc[e] = expf(lg[e] - mx); s += sc[e]; }
        float inv = 1.f / s;
#pragma unroll
        for (int e = 0; e < NEXP; e++) sc[e] *= inv;

        int   idx[KTOP];
        float wv [KTOP];
        float wsum = 0.f;
#pragma unroll
        for (int k = 0; k < KTOP; k++) {
            int   bi = 0;
            float bv = -1.f;
#pragma unroll
            for (int e = 0; e < NEXP; e++)
                if (sc[e] > bv) { bv = sc[e]; bi = e; }
            idx[k] = bi; wv[k] = bv; wsum += bv;
            sc[bi] = -2.f;
        }
        float winv = 1.f / (wsum + 1e-20f);
#pragma unroll
        for (int k = 0; k < KTOP; k++) {
            g_ti[t * KTOP + k] = idx[k];
            g_tw[t * KTOP + k] = wv[k] * winv;
            atomicAdd(&g_cnt[idx[k]], 1);
        }
    }
}

__global__ void offsets_kernel() {
    if (threadIdx.x == 0) {
        int cum = 0;
        for (int e = 0; e < NEXP; e++) {
            g_off[e] = cum;
            cum += g_cnt[e];
            g_cur[e] = 0;
        }
    }
}

__global__ void scatter_kernel() {
    int t = blockIdx.x * blockDim.x + threadIdx.x;
    if (t >= TOK) return;
#pragma unroll
    for (int k = 0; k < KTOP; k++) {
        int e = g_ti[t * KTOP + k];
        int pos = atomicAdd(&g_cur[e], 1);
        int s = g_off[e] + pos;
        g_ptok[s] = t;
        g_pexp[s] = e;
        g_t2s[t * KTOP + k] = s;
    }
}

// ---------------- 128x128x8 register-tiled SGEMM (NT, bias epilogue) ----------------
template <bool GATHER>
__device__ __forceinline__ void sgemm128(
    const float* __restrict__ A, int lda, const int* __restrict__ ridx, int M,
    const float* __restrict__ B, int ldb, const float* __restrict__ bias,
    float* __restrict__ C, int ldc, int K)
{
    const int BM = 128, BN = 128, BK = 8;
    __shared__ float As[BK][BM];
    __shared__ float Bs[BK][BN];
    int tid = threadIdx.x;                 // 256 threads
    int m0 = blockIdx.y * BM;
    if (m0 >= M) return;
    int n0 = blockIdx.x * BN;

    int tx = tid & 15;                     // 16 x 16 thread grid
    int ty = tid >> 4;

    int ar = tid >> 1;                     // loader: row 0..127
    int ac = (tid & 1) * 4;                // col 0 or 4

    int gm = m0 + ar;
    const float* aptr = nullptr;
    if (gm < M) {
        int row = GATHER ? ridx[gm] : gm;
        aptr = A + (size_t)row * lda;
    }
    const float* bptr = B + (size_t)(n0 + ar) * ldb;

    float acc[8][8];
#pragma unroll
    for (int i = 0; i < 8; i++)
#pragma unroll
        for (int j = 0; j < 8; j++) acc[i][j] = 0.f;

    for (int k0 = 0; k0 < K; k0 += BK) {
        float4 av = aptr ? *(const float4*)(aptr + k0 + ac)
                         : make_float4(0.f, 0.f, 0.f, 0.f);
        float4 bv = *(const float4*)(bptr + k0 + ac);
        __syncthreads();
        As[ac + 0][ar] = av.x; As[ac + 1][ar] = av.y;
        As[ac + 2][ar] = av.z; As[ac + 3][ar] = av.w;
        Bs[ac + 0][ar] = bv.x; Bs[ac + 1][ar] = bv.y;
        Bs[ac + 2][ar] = bv.z; Bs[ac + 3][ar] = bv.w;
        __syncthreads();
#pragma unroll
        for (int k = 0; k < BK; k++) {
            float a0[8], b0[8];
#pragma unroll
            for (int i = 0; i < 8; i++) a0[i] = As[k][ty * 8 + i];
#pragma unroll
            for (int j = 0; j < 8; j++) b0[j] = Bs[k][tx * 8 + j];
#pragma unroll
            for (int i = 0; i < 8; i++)
#pragma unroll
                for (int j = 0; j < 8; j++) acc[i][j] += a0[i] * b0[j];
        }
    }

#pragma unroll
    for (int i = 0; i < 8; i++) {
        int m = m0 + ty * 8 + i;
        if (m < M) {
            float* cp = C + (size_t)m * ldc + n0 + tx * 8;
            const float* bp = bias + n0 + tx * 8;
#pragma unroll
            for (int j = 0; j < 8; j++) cp[j] = acc[i][j] + bp[j];
        }
    }
}

// ---------------- GEMM wrappers ----------------
__global__ void k_efc1(const float* __restrict__ x,
                       const float* __restrict__ w,
                       const float* __restrict__ b) {
    int e = blockIdx.z;
    int M = g_cnt[e], off = g_off[e];
    sgemm128<true>(x, DDIM, g_ptok + off, M,
                   w + (size_t)e * 2 * FF * DDIM, DDIM, b + (size_t)e * 2 * FF,
                   g_h + (size_t)off * 2 * FF, 2 * FF, DDIM);
}

__global__ void k_efc2(const float* __restrict__ w,
                       const float* __restrict__ b) {
    int e = blockIdx.z;
    int M = g_cnt[e], off = g_off[e];
    sgemm128<false>(g_a + (size_t)off * FF, FF, nullptr, M,
                    w + (size_t)e * DDIM * FF, FF, b + (size_t)e * DDIM,
                    g_yp + (size_t)off * DDIM, DDIM, FF);
}

__global__ void k_sfc1(const float* __restrict__ x,
                       const float* __restrict__ w,
                       const float* __restrict__ b) {
    sgemm128<false>(x, DDIM, nullptr, TOK, w, DDIM, b, g_hs, 2 * FSH, DDIM);
}

__global__ void k_sfc2(const float* __restrict__ w,
                       const float* __restrict__ b,
                       float* __restrict__ out) {
    sgemm128<false>(g_as, FSH, nullptr, TOK, w, FSH, b, out, DDIM, FSH);
}

// ---------------- elementwise ----------------
__global__ void k_geglu_e(const float* __restrict__ gm) {
    int i = blockIdx.x * blockDim.x + threadIdx.x;       // float4 index
    const int F4 = FF / 4;
    if (i >= NPAIR * F4) return;
    int p = i / F4, f4 = i % F4;
    int e = g_pexp[p];
    const float4 xh = *(const float4*)(g_h + (size_t)p * 2 * FF + f4 * 4);
    const float4 gg = *(const float4*)(g_h + (size_t)p * 2 * FF + FF + f4 * 4);
    const float4 mu = *(const float4*)(gm + (size_t)e * FF + f4 * 4);
    float4 r;
    r.x = gelu_exact(gg.x) * xh.x * mu.x;
    r.y = gelu_exact(gg.y) * xh.y * mu.y;
    r.z = gelu_exact(gg.z) * xh.z * mu.z;
    r.w = gelu_exact(gg.w) * xh.w * mu.w;
    *(float4*)(g_a + (size_t)p * FF + f4 * 4) = r;
}

__global__ void k_geglu_s(const float* __restrict__ gm) {
    int i = blockIdx.x * blockDim.x + threadIdx.x;       // float4 index
    const int F4 = FSH / 4;
    if (i >= TOK * F4) return;
    int t = i / F4, f4 = i % F4;
    const float4 xh = *(const float4*)(g_hs + (size_t)t * 2 * FSH + f4 * 4);
    const float4 gg = *(const float4*)(g_hs + (size_t)t * 2 * FSH + FSH + f4 * 4);
    const float4 mu = *(const float4*)(gm + f4 * 4);
    float4 r;
    r.x = gelu_exact(gg.x) * xh.x * mu.x;
    r.y = gelu_exact(gg.y) * xh.y * mu.y;
    r.z = gelu_exact(gg.z) * xh.z * mu.z;
    r.w = gelu_exact(gg.w) * xh.w * mu.w;
    *(float4*)(g_as + (size_t)t * FSH + f4 * 4) = r;
}

__global__ void k_comb(float* __restrict__ out) {
    int i = blockIdx.x * blockDim.x + threadIdx.x;       // float4 index over TOK*DDIM
    const int D4 = DDIM / 4;
    if (i >= TOK * D4) return;
    int t = i / D4, d4 = i % D4;
    float4 acc = *(float4*)(out + (size_t)t * DDIM + d4 * 4);
#pragma unroll
    for (int k = 0; k < KTOP; k++) {
        int s = g_t2s[t * KTOP + k];
        float w = g_tw[t * KTOP + k];
        const float4 v = *(const float4*)(g_yp + (size_t)s * DDIM + d4 * 4);
        acc.x += w * v.x; acc.y += w * v.y; acc.z += w * v.z; acc.w += w * v.w;
    }
    *(float4*)(out + (size_t)t * DDIM + d4 * 4) = acc;
}

// ---------------- launch ----------------
extern "C" void kernel_launch(void* const* d_in, const int* in_sizes, int n_in,
                              void* d_out, int out_size) {
    const float* x       = (const float*)d_in[0];
    const float* gate_w  = (const float*)d_in[1];
    const float* fc1_w   = (const float*)d_in[2];
    const float* fc1_b   = (const float*)d_in[3];
    const float* gmult   = (const float*)d_in[4];
    const float* fc2_w   = (const float*)d_in[5];
    const float* fc2_b   = (const float*)d_in[6];
    const float* sfc1_w  = (const float*)d_in[7];
    const float* sfc1_b  = (const float*)d_in[8];
    const float* sgmult  = (const float*)d_in[9];
    const float* sfc2_w  = (const float*)d_in[10];
    const float* sfc2_b  = (const float*)d_in[11];
    float* out = (float*)d_out;

    zero_kernel<<<1, 32>>>();
    gate_kernel<<<TOK, 128>>>(x, gate_w);
    offsets_kernel<<<1, 1>>>();
    scatter_kernel<<<(TOK + 255) / 256, 256>>>();

    // expert fc1: N = 2F = 2048
    dim3 g1(2 * FF / 128, TOK / 128, NEXP);
    k_efc1<<<g1, 256>>>(x, fc1_w, fc1_b);
    k_geglu_e<<<(NPAIR * (FF / 4) + 255) / 256, 256>>>(gmult);

    // expert fc2: N = D = 1024
    dim3 g2(DDIM / 128, TOK / 128, NEXP);
    k_efc2<<<g2, 256>>>(fc2_w, fc2_b);

    // shared expert
    dim3 g3(2 * FSH / 128, TOK / 128);
    k_sfc1<<<g3, 256>>>(x, sfc1_w, sfc1_b);
    k_geglu_s<<<(TOK * (FSH / 4) + 255) / 256, 256>>>(sgmult);
    dim3 g4(DDIM / 128, TOK / 128);
    k_sfc2<<<g4, 256>>>(sfc2_w, sfc2_b, out);

    k_comb<<<(TOK * (DDIM / 4) + 255) / 256, 256>>>(out);
}

// round 3
// speedup vs baseline: 1.3150x; 1.3150x over previous
#include <cuda_runtime.h>
#include <cuda_bf16.h>
#include <math.h>
#include <stdint.h>

#define TOK   2048
#define DDIM  1024
#define NEXP  15
#define KTOP  3
#define FF    1024
#define FSH   2048
#define NPAIR (TOK*KTOP)   // 6144

// ---------------- static scratch (no allocations allowed) ----------------
__device__ __align__(16) float g_h [(size_t)NPAIR * 2 * FF];   // expert fc1 out
__device__ __align__(16) float g_a [(size_t)NPAIR * FF];       // expert geglu out
__device__ __align__(16) float g_yp[(size_t)NPAIR * DDIM];     // expert fc2 out
__device__ __align__(16) float g_hs[(size_t)TOK * 2 * FSH];    // shared fc1 out
__device__ __align__(16) float g_as[(size_t)TOK * FSH];        // shared geglu out
__device__ int   g_ptok[NPAIR];
__device__ int   g_pexp[NPAIR];
__device__ int   g_t2s [TOK * KTOP];
__device__ float g_tw  [TOK * KTOP];
__device__ int   g_ti  [TOK * KTOP];
__device__ int   g_cnt[NEXP], g_off[NEXP], g_cur[NEXP];

__device__ __forceinline__ float gelu_exact(float v) {
    return 0.5f * v * (1.0f + erff(v * 0.70710678118654752440f));
}
__device__ __forceinline__ uint32_t smem_u32(const void* p) {
    return (uint32_t)__cvta_generic_to_shared(p);
}

// ---------------- gating ----------------
__global__ void zero_kernel() {
    int i = threadIdx.x;
    if (i < NEXP) g_cnt[i] = 0;
}

__global__ void gate_kernel(const float* __restrict__ x, const float* __restrict__ gw) {
    int t = blockIdx.x;
    int tid = threadIdx.x;   // 128 threads
    float part[NEXP];
#pragma unroll
    for (int e = 0; e < NEXP; e++) part[e] = 0.f;
    const float* xr = x + (size_t)t * DDIM;
    for (int d = tid; d < DDIM; d += 128) {
        float xv = xr[d];
#pragma unroll
        for (int e = 0; e < NEXP; e++) part[e] += xv * gw[e * DDIM + d];
    }
#pragma unroll
    for (int e = 0; e < NEXP; e++)
#pragma unroll
        for (int o = 16; o > 0; o >>= 1)
            part[e] += __shfl_xor_sync(0xFFFFFFFFu, part[e], o);

    __shared__ float red[NEXP][4];
    int w = tid >> 5, l = tid & 31;
    if (l == 0)
#pragma unroll
        for (int e = 0; e < NEXP; e++) red[e][w] = part[e];
    __syncthreads();

    if (tid == 0) {
        float lg[NEXP];
#pragma unroll
        for (int e = 0; e < NEXP; e++)
            lg[e] = red[e][0] + red[e][1] + red[e][2] + red[e][3];
        float mx = lg[0];
#pragma unroll
        for (int e = 1; e < NEXP; e++) mx = fmaxf(mx, lg[e]);
        float s = 0.f, sc[NEXP];
#pragma unroll
        for (int e = 0; e < NEXP; e++) { sc[e] = expf(lg[e] - mx); s += sc[e]; }
        float inv = 1.f / s;
#pragma unroll
        for (int e = 0; e < NEXP; e++) sc[e] *= inv;

        int   idx[KTOP];
        float wv [KTOP];
        float wsum = 0.f;
#pragma unroll
        for (int k = 0; k < KTOP; k++) {
            int   bi = 0;
            float bv = -1.f;
#pragma unroll
            for (int e = 0; e < NEXP; e++)
                if (sc[e] > bv) { bv = sc[e]; bi = e; }
            idx[k] = bi; wv[k] = bv; wsum += bv;
            sc[bi] = -2.f;
        }
        float winv = 1.f / (wsum + 1e-20f);
#pragma unroll
        for (int k = 0; k < KTOP; k++) {
            g_ti[t * KTOP + k] = idx[k];
            g_tw[t * KTOP + k] = wv[k] * winv;
            atomicAdd(&g_cnt[idx[k]], 1);
        }
    }
}

__global__ void offsets_kernel() {
    if (threadIdx.x == 0) {
        int cum = 0;
        for (int e = 0; e < NEXP; e++) {
            g_off[e] = cum;
            cum += g_cnt[e];
            g_cur[e] = 0;
        }
    }
}

__global__ void scatter_kernel() {
    int t = blockIdx.x * blockDim.x + threadIdx.x;
    if (t >= TOK) return;
#pragma unroll
    for (int k = 0; k < KTOP; k++) {
        int e = g_ti[t * KTOP + k];
        int pos = atomicAdd(&g_cur[e], 1);
        int s = g_off[e] + pos;
        g_ptok[s] = t;
        g_pexp[s] = e;
        g_t2s[t * KTOP + k] = s;
    }
}

// ---------------- mma.sync bf16 hi/lo split GEMM ----------------
// C(MxN) = A(MxK) * B(NxK)^T + bias, fp32 in/out.
// CTA tile 128x128, 8 warps (2x4) of 64x32 warp tiles, K-chunk 32, double buffer.
#define TS 80                         // smem row stride in bytes (32 bf16 data + pad)
#define TILE_B (128*TS)               // 10240 per tile
#define STAGE_B (4*TILE_B)            // Ah,Al,Bh,Bl
#define SMEM_GEMM (2*STAGE_B)         // 81920

extern __shared__ char smem_dyn[];

__device__ __forceinline__ void ldsm4(uint32_t* r, uint32_t addr) {
    asm volatile("ldmatrix.sync.aligned.m8n8.x4.shared.b16 {%0,%1,%2,%3}, [%4];"
                 : "=r"(r[0]), "=r"(r[1]), "=r"(r[2]), "=r"(r[3]) : "r"(addr));
}
__device__ __forceinline__ void mma16816(float* d, const uint32_t* a, const uint32_t* b) {
    asm volatile("mma.sync.aligned.m16n8k16.row.col.f32.bf16.bf16.f32 "
                 "{%0,%1,%2,%3},{%4,%5,%6,%7},{%8,%9},{%0,%1,%2,%3};"
                 : "+f"(d[0]), "+f"(d[1]), "+f"(d[2]), "+f"(d[3])
                 : "r"(a[0]), "r"(a[1]), "r"(a[2]), "r"(a[3]), "r"(b[0]), "r"(b[1]));
}

// pack 4 floats into hi (2x u32 of bf16x2) and lo
__device__ __forceinline__ void hilo4(float4 v, uint2& hv, uint2& lv) {
    __nv_bfloat16 h0 = __float2bfloat16_rn(v.x);
    __nv_bfloat16 h1 = __float2bfloat16_rn(v.y);
    __nv_bfloat16 h2 = __float2bfloat16_rn(v.z);
    __nv_bfloat16 h3 = __float2bfloat16_rn(v.w);
    __nv_bfloat16 l0 = __float2bfloat16_rn(v.x - __bfloat162float(h0));
    __nv_bfloat16 l1 = __float2bfloat16_rn(v.y - __bfloat162float(h1));
    __nv_bfloat16 l2 = __float2bfloat16_rn(v.z - __bfloat162float(h2));
    __nv_bfloat16 l3 = __float2bfloat16_rn(v.w - __bfloat162float(h3));
    hv.x = ((uint32_t)*(unsigned short*)&h1 << 16) | *(unsigned short*)&h0;
    hv.y = ((uint32_t)*(unsigned short*)&h3 << 16) | *(unsigned short*)&h2;
    lv.x = ((uint32_t)*(unsigned short*)&l1 << 16) | *(unsigned short*)&l0;
    lv.y = ((uint32_t)*(unsigned short*)&l3 << 16) | *(unsigned short*)&l2;
}

template <bool GATHER>
__device__ void mm_gemm(const float* __restrict__ A, int lda,
                        const int* __restrict__ ridx, int M,
                        const float* __restrict__ B, int ldb,
                        const float* __restrict__ bias,
                        float* __restrict__ C, int ldc, int K)
{
    int m0 = blockIdx.y * 128;
    if (m0 >= M) return;
    int n0 = blockIdx.x * 128;

    int tid = threadIdx.x;             // 256
    int wid = tid >> 5, lane = tid & 31;
    char* sm = smem_dyn;
    uint32_t sBase = smem_u32(sm);

    // ---- loader mapping: 2 threads per row, 16 floats each ----
    int lrow = tid >> 1;
    int lhalf = tid & 1;               // k offset 0 / 16
    const float* arow = nullptr;
    int gm = m0 + lrow;
    if (gm < M) {
        int r = GATHER ? ridx[gm] : gm;
        arow = A + (size_t)r * lda;
    }
    const float* brow = B + (size_t)(n0 + lrow) * ldb;
    uint32_t stoff = (uint32_t)(lrow * TS + lhalf * 32);   // + q*8

    // ---- warp tile ----
    int wm = wid >> 2;                 // 0..1 -> m offset wm*64
    int wn = wid & 3;                  // 0..3 -> n offset wn*32
    // ldmatrix base offsets within a tile
    uint32_t aoff = (uint32_t)((wm * 64 + (lane & 15)) * TS) + ((lane >> 4) << 4);
    uint32_t boff = (uint32_t)((wn * 32 + (lane & 7) + ((lane >> 4) & 1) * 8) * TS)
                  + (((lane >> 3) & 1) << 4);

    float acc[4][4][4];
#pragma unroll
    for (int i = 0; i < 4; i++)
#pragma unroll
        for (int j = 0; j < 4; j++)
#pragma unroll
            for (int c = 0; c < 4; c++) acc[i][j][c] = 0.f;

    float4 av[4], bv[4];
    // prefetch iter 0
#pragma unroll
    for (int q = 0; q < 4; q++) {
        int k = lhalf * 16 + q * 4;
        av[q] = arow ? *(const float4*)(arow + k) : make_float4(0.f, 0.f, 0.f, 0.f);
        bv[q] = *(const float4*)(brow + k);
    }

    int NT = K / 32;
    for (int it = 0; it < NT; it++) {
        uint32_t stg = (uint32_t)(it & 1) * STAGE_B;
        // store current regs -> smem
        char* pAh = sm + stg + stoff;
        char* pAl = pAh + TILE_B;
        char* pBh = pAl + TILE_B;
        char* pBl = pBh + TILE_B;
#pragma unroll
        for (int q = 0; q < 4; q++) {
            uint2 hv, lv;
            hilo4(av[q], hv, lv);
            *(uint2*)(pAh + q * 8) = hv;
            *(uint2*)(pAl + q * 8) = lv;
            hilo4(bv[q], hv, lv);
            *(uint2*)(pBh + q * 8) = hv;
            *(uint2*)(pBl + q * 8) = lv;
        }
        __syncthreads();

        // prefetch next chunk
        if (it + 1 < NT) {
            int k0 = (it + 1) * 32 + lhalf * 16;
#pragma unroll
            for (int q = 0; q < 4; q++) {
                av[q] = arow ? *(const float4*)(arow + k0 + q * 4)
                             : make_float4(0.f, 0.f, 0.f, 0.f);
                bv[q] = *(const float4*)(brow + k0 + q * 4);
            }
        }

        // MMA over this stage
        uint32_t Ah = sBase + stg + aoff;
        uint32_t Al = Ah + TILE_B;
        uint32_t Bh = sBase + stg + 2 * TILE_B + boff;
        uint32_t Bl = Bh + TILE_B;
#pragma unroll
        for (int k16 = 0; k16 < 2; k16++) {
            uint32_t ah[4][4], al[4][4], bh[2][4], bl[2][4];
#pragma unroll
            for (int i = 0; i < 4; i++) ldsm4(ah[i], Ah + i * 16 * TS + k16 * 32);
#pragma unroll
            for (int i = 0; i < 4; i++) ldsm4(al[i], Al + i * 16 * TS + k16 * 32);
#pragma unroll
            for (int jj = 0; jj < 2; jj++) ldsm4(bh[jj], Bh + jj * 16 * TS + k16 * 32);
#pragma unroll
            for (int jj = 0; jj < 2; jj++) ldsm4(bl[jj], Bl + jj * 16 * TS + k16 * 32);
#pragma unroll
            for (int i = 0; i < 4; i++)
#pragma unroll
                for (int j = 0; j < 4; j++) {
                    const uint32_t* bhp = &bh[j >> 1][(j & 1) * 2];
                    const uint32_t* blp = &bl[j >> 1][(j & 1) * 2];
                    mma16816(acc[i][j], ah[i], bhp);
                    mma16816(acc[i][j], al[i], bhp);
                    mma16816(acc[i][j], ah[i], blp);
                }
        }
        __syncthreads();
    }

    // ---- epilogue: regs -> gmem with bias ----
    int rbase = m0 + wm * 64 + (lane >> 2);
    int cbase = n0 + wn * 32 + (lane & 3) * 2;
#pragma unroll
    for (int i = 0; i < 4; i++) {
#pragma unroll
        for (int j = 0; j < 4; j++) {
            int r = rbase + i * 16;
            int c = cbase + j * 8;
            float b0 = bias[c], b1 = bias[c + 1];
            if (r < M) {
                float2 o = make_float2(acc[i][j][0] + b0, acc[i][j][1] + b1);
                *(float2*)(C + (size_t)r * ldc + c) = o;
            }
            if (r + 8 < M) {
                float2 o = make_float2(acc[i][j][2] + b0, acc[i][j][3] + b1);
                *(float2*)(C + (size_t)(r + 8) * ldc + c) = o;
            }
        }
    }
}

// ---------------- GEMM wrappers ----------------
__global__ void __launch_bounds__(256, 1) k_efc1(const float* __restrict__ x,
                                                 const float* __restrict__ w,
                                                 const float* __restrict__ b) {
    int e = blockIdx.z;
    int M = g_cnt[e], off = g_off[e];
    mm_gemm<true>(x, DDIM, g_ptok + off, M,
                  w + (size_t)e * 2 * FF * DDIM, DDIM, b + (size_t)e * 2 * FF,
                  g_h + (size_t)off * 2 * FF, 2 * FF, DDIM);
}

__global__ void __launch_bounds__(256, 1) k_efc2(const float* __restrict__ w,
                                                 const float* __restrict__ b) {
    int e = blockIdx.z;
    int M = g_cnt[e], off = g_off[e];
    mm_gemm<false>(g_a + (size_t)off * FF, FF, nullptr, M,
                   w + (size_t)e * DDIM * FF, FF, b + (size_t)e * DDIM,
                   g_yp + (size_t)off * DDIM, DDIM, FF);
}

__global__ void __launch_bounds__(256, 1) k_sfc1(const float* __restrict__ x,
                                                 const float* __restrict__ w,
                                                 const float* __restrict__ b) {
    mm_gemm<false>(x, DDIM, nullptr, TOK, w, DDIM, b, g_hs, 2 * FSH, DDIM);
}

__global__ void __launch_bounds__(256, 1) k_sfc2(const float* __restrict__ w,
                                                 const float* __restrict__ b,
                                                 float* __restrict__ out) {
    mm_gemm<false>(g_as, FSH, nullptr, TOK, w, FSH, b, out, DDIM, FSH);
}

// ---------------- elementwise ----------------
__global__ void k_geglu_e(const float* __restrict__ gm) {
    int i = blockIdx.x * blockDim.x + threadIdx.x;
    const int F4 = FF / 4;
    if (i >= NPAIR * F4) return;
    int p = i / F4, f4 = i % F4;
    int e = g_pexp[p];
    const float4 xh = *(const float4*)(g_h + (size_t)p * 2 * FF + f4 * 4);
    const float4 gg = *(const float4*)(g_h + (size_t)p * 2 * FF + FF + f4 * 4);
    const float4 mu = *(const float4*)(gm + (size_t)e * FF + f4 * 4);
    float4 r;
    r.x = gelu_exact(gg.x) * xh.x * mu.x;
    r.y = gelu_exact(gg.y) * xh.y * mu.y;
    r.z = gelu_exact(gg.z) * xh.z * mu.z;
    r.w = gelu_exact(gg.w) * xh.w * mu.w;
    *(float4*)(g_a + (size_t)p * FF + f4 * 4) = r;
}

__global__ void k_geglu_s(const float* __restrict__ gm) {
    int i = blockIdx.x * blockDim.x + threadIdx.x;
    const int F4 = FSH / 4;
    if (i >= TOK * F4) return;
    int t = i / F4, f4 = i % F4;
    const float4 xh = *(const float4*)(g_hs + (size_t)t * 2 * FSH + f4 * 4);
    const float4 gg = *(const float4*)(g_hs + (size_t)t * 2 * FSH + FSH + f4 * 4);
    const float4 mu = *(const float4*)(gm + f4 * 4);
    float4 r;
    r.x = gelu_exact(gg.x) * xh.x * mu.x;
    r.y = gelu_exact(gg.y) * xh.y * mu.y;
    r.z = gelu_exact(gg.z) * xh.z * mu.z;
    r.w = gelu_exact(gg.w) * xh.w * mu.w;
    *(float4*)(g_as + (size_t)t * FSH + f4 * 4) = r;
}

__global__ void k_comb(float* __restrict__ out) {
    int i = blockIdx.x * blockDim.x + threadIdx.x;
    const int D4 = DDIM / 4;
    if (i >= TOK * D4) return;
    int t = i / D4, d4 = i % D4;
    float4 acc = *(float4*)(out + (size_t)t * DDIM + d4 * 4);
#pragma unroll
    for (int k = 0; k < KTOP; k++) {
        int s = g_t2s[t * KTOP + k];
        float w = g_tw[t * KTOP + k];
        const float4 v = *(const float4*)(g_yp + (size_t)s * DDIM + d4 * 4);
        acc.x += w * v.x; acc.y += w * v.y; acc.z += w * v.z; acc.w += w * v.w;
    }
    *(float4*)(out + (size_t)t * DDIM + d4 * 4) = acc;
}

// ---------------- launch ----------------
extern "C" void kernel_launch(void* const* d_in, const int* in_sizes, int n_in,
                              void* d_out, int out_size) {
    const float* x       = (const float*)d_in[0];
    const float* gate_w  = (const float*)d_in[1];
    const float* fc1_w   = (const float*)d_in[2];
    const float* fc1_b   = (const float*)d_in[3];
    const float* gmult   = (const float*)d_in[4];
    const float* fc2_w   = (const float*)d_in[5];
    const float* fc2_b   = (const float*)d_in[6];
    const float* sfc1_w  = (const float*)d_in[7];
    const float* sfc1_b  = (const float*)d_in[8];
    const float* sgmult  = (const float*)d_in[9];
    const float* sfc2_w  = (const float*)d_in[10];
    const float* sfc2_b  = (const float*)d_in[11];
    float* out = (float*)d_out;

    cudaFuncSetAttribute(k_efc1, cudaFuncAttributeMaxDynamicSharedMemorySize, SMEM_GEMM);
    cudaFuncSetAttribute(k_efc2, cudaFuncAttributeMaxDynamicSharedMemorySize, SMEM_GEMM);
    cudaFuncSetAttribute(k_sfc1, cudaFuncAttributeMaxDynamicSharedMemorySize, SMEM_GEMM);
    cudaFuncSetAttribute(k_sfc2, cudaFuncAttributeMaxDynamicSharedMemorySize, SMEM_GEMM);

    zero_kernel<<<1, 32>>>();
    gate_kernel<<<TOK, 128>>>(x, gate_w);
    offsets_kernel<<<1, 1>>>();
    scatter_kernel<<<(TOK + 255) / 256, 256>>>();

    // expert fc1: N = 2F = 2048
    dim3 g1(2 * FF / 128, NPAIR / 128, NEXP);
    k_efc1<<<g1, 256, SMEM_GEMM>>>(x, fc1_w, fc1_b);
    k_geglu_e<<<(NPAIR * (FF / 4) + 255) / 256, 256>>>(gmult);

    // expert fc2: N = D = 1024
    dim3 g2(DDIM / 128, NPAIR / 128, NEXP);
    k_efc2<<<g2, 256, SMEM_GEMM>>>(fc2_w, fc2_b);

    // shared expert
    dim3 g3(2 * FSH / 128, TOK / 128);
    k_sfc1<<<g3, 256, SMEM_GEMM>>>(x, sfc1_w, sfc1_b);
    k_geglu_s<<<(TOK * (FSH / 4) + 255) / 256, 256>>>(sgmult);
    dim3 g4(DDIM / 128, TOK / 128);
    k_sfc2<<<g4, 256, SMEM_GEMM>>>(sfc2_w, sfc2_b, out);

    k_comb<<<(TOK * (DDIM / 4) + 255) / 256, 256>>>(out);
}

// round 4
// speedup vs baseline: 2.4061x; 1.8296x over previous
#include <cuda_runtime.h>
#include <cuda_bf16.h>
#include <math.h>
#include <stdint.h>

#define TOK   2048
#define DDIM  1024
#define NEXP  15
#define KTOP  3
#define FF    1024
#define FSH   2048
#define NPAIR (TOK*KTOP)   // 6144

// ---------------- static scratch ----------------
__device__ __align__(16) float g_h [(size_t)NPAIR * 2 * FF];      // expert fc1 out (fp32)
__device__ __align__(16) float g_yp[(size_t)NPAIR * DDIM];        // expert fc2 out
__device__ __align__(16) float g_hs[(size_t)TOK * 2 * FSH];       // shared fc1 out
__device__ __align__(16) float g_out_tmp[1];                      // unused
// bf16 hi/lo operand arrays
__device__ __align__(16) __nv_bfloat16 g_xh[(size_t)TOK * DDIM],  g_xl[(size_t)TOK * DDIM];
__device__ __align__(16) __nv_bfloat16 g_ah[(size_t)NPAIR * FF],  g_al[(size_t)NPAIR * FF];
__device__ __align__(16) __nv_bfloat16 g_ash[(size_t)TOK * FSH],  g_asl[(size_t)TOK * FSH];
__device__ __align__(16) __nv_bfloat16 g_w1h[(size_t)NEXP * 2 * FF * DDIM], g_w1l[(size_t)NEXP * 2 * FF * DDIM];
__device__ __align__(16) __nv_bfloat16 g_w2h[(size_t)NEXP * DDIM * FF],     g_w2l[(size_t)NEXP * DDIM * FF];
__device__ __align__(16) __nv_bfloat16 g_s1h[(size_t)2 * FSH * DDIM],       g_s1l[(size_t)2 * FSH * DDIM];
__device__ __align__(16) __nv_bfloat16 g_s2h[(size_t)DDIM * FSH],           g_s2l[(size_t)DDIM * FSH];

__device__ int   g_ptok[NPAIR];
__device__ int   g_pexp[NPAIR];
__device__ int   g_t2s [TOK * KTOP];
__device__ float g_tw  [TOK * KTOP];
__device__ int   g_ti  [TOK * KTOP];
__device__ int   g_cnt[NEXP], g_off[NEXP], g_cur[NEXP];

__device__ __forceinline__ float gelu_exact(float v) {
    return 0.5f * v * (1.0f + erff(v * 0.70710678118654752440f));
}
__device__ __forceinline__ uint32_t smem_u32(const void* p) {
    return (uint32_t)__cvta_generic_to_shared(p);
}

// pack 4 floats into hi/lo bf16 pairs
__device__ __forceinline__ void hilo4(float4 v, uint2& hv, uint2& lv) {
    __nv_bfloat16 h0 = __float2bfloat16_rn(v.x);
    __nv_bfloat16 h1 = __float2bfloat16_rn(v.y);
    __nv_bfloat16 h2 = __float2bfloat16_rn(v.z);
    __nv_bfloat16 h3 = __float2bfloat16_rn(v.w);
    __nv_bfloat16 l0 = __float2bfloat16_rn(v.x - __bfloat162float(h0));
    __nv_bfloat16 l1 = __float2bfloat16_rn(v.y - __bfloat162float(h1));
    __nv_bfloat16 l2 = __float2bfloat16_rn(v.z - __bfloat162float(h2));
    __nv_bfloat16 l3 = __float2bfloat16_rn(v.w - __bfloat162float(h3));
    hv.x = ((uint32_t)*(unsigned short*)&h1 << 16) | *(unsigned short*)&h0;
    hv.y = ((uint32_t)*(unsigned short*)&h3 << 16) | *(unsigned short*)&h2;
    lv.x = ((uint32_t)*(unsigned short*)&l1 << 16) | *(unsigned short*)&l0;
    lv.y = ((uint32_t)*(unsigned short*)&l3 << 16) | *(unsigned short*)&l2;
}

// ---------------- conversion kernel (fp32 -> bf16 hi/lo) ----------------
__global__ void k_cvt(const float* __restrict__ src, __nv_bfloat16* __restrict__ dh,
                      __nv_bfloat16* __restrict__ dl, int n4) {
    int i = blockIdx.x * blockDim.x + threadIdx.x;
    if (i >= n4) return;
    float4 v = ((const float4*)src)[i];
    uint2 hv, lv;
    hilo4(v, hv, lv);
    ((uint2*)dh)[i] = hv;
    ((uint2*)dl)[i] = lv;
}

// ---------------- gating ----------------
__global__ void zero_kernel() {
    int i = threadIdx.x;
    if (i < NEXP) g_cnt[i] = 0;
}

__global__ void gate_kernel(const float* __restrict__ x, const float* __restrict__ gw) {
    int t = blockIdx.x;
    int tid = threadIdx.x;   // 128 threads
    float part[NEXP];
#pragma unroll
    for (int e = 0; e < NEXP; e++) part[e] = 0.f;
    const float* xr = x + (size_t)t * DDIM;
    for (int d = tid; d < DDIM; d += 128) {
        float xv = xr[d];
#pragma unroll
        for (int e = 0; e < NEXP; e++) part[e] += xv * gw[e * DDIM + d];
    }
#pragma unroll
    for (int e = 0; e < NEXP; e++)
#pragma unroll
        for (int o = 16; o > 0; o >>= 1)
            part[e] += __shfl_xor_sync(0xFFFFFFFFu, part[e], o);

    __shared__ float red[NEXP][4];
    int w = tid >> 5, l = tid & 31;
    if (l == 0)
#pragma unroll
        for (int e = 0; e < NEXP; e++) red[e][w] = part[e];
    __syncthreads();

    if (tid == 0) {
        float lg[NEXP];
#pragma unroll
        for (int e = 0; e < NEXP; e++)
            lg[e] = red[e][0] + red[e][1] + red[e][2] + red[e][3];
        float mx = lg[0];
#pragma unroll
        for (int e = 1; e < NEXP; e++) mx = fmaxf(mx, lg[e]);
        float s = 0.f, sc[NEXP];
#pragma unroll
        for (int e = 0; e < NEXP; e++) { sc[e] = expf(lg[e] - mx); s += sc[e]; }
        float inv = 1.f / s;
#pragma unroll
        for (int e = 0; e < NEXP; e++) sc[e] *= inv;

        int   idx[KTOP];
        float wv [KTOP];
        float wsum = 0.f;
#pragma unroll
        for (int k = 0; k < KTOP; k++) {
            int   bi = 0;
            float bv = -1.f;
#pragma unroll
            for (int e = 0; e < NEXP; e++)
                if (sc[e] > bv) { bv = sc[e]; bi = e; }
            idx[k] = bi; wv[k] = bv; wsum += bv;
            sc[bi] = -2.f;
        }
        float winv = 1.f / (wsum + 1e-20f);
#pragma unroll
        for (int k = 0; k < KTOP; k++) {
            g_ti[t * KTOP + k] = idx[k];
            g_tw[t * KTOP + k] = wv[k] * winv;
            atomicAdd(&g_cnt[idx[k]], 1);
        }
    }
}

__global__ void offsets_kernel() {
    if (threadIdx.x == 0) {
        int cum = 0;
        for (int e = 0; e < NEXP; e++) {
            g_off[e] = cum;
            cum += g_cnt[e];
            g_cur[e] = 0;
        }
    }
}

__global__ void scatter_kernel() {
    int t = blockIdx.x * blockDim.x + threadIdx.x;
    if (t >= TOK) return;
#pragma unroll
    for (int k = 0; k < KTOP; k++) {
        int e = g_ti[t * KTOP + k];
        int pos = atomicAdd(&g_cur[e], 1);
        int s = g_off[e] + pos;
        g_ptok[s] = t;
        g_pexp[s] = e;
        g_t2s[t * KTOP + k] = s;
    }
}

// ---------------- mma.sync bf16 hi/lo GEMM with cp.async pipeline ----------------
// C(MxN) = (Ah+Al)(MxK) * ((Bh+Bl)(NxK))^T + bias,  operands bf16, accum/out fp32.
// CTA tile 128x128, 8 warps (2x4) -> 64x32 warp tiles, K-chunk 32, 3-stage cp.async ring.
#define BK  32
#define TS  80                        // smem row stride bytes (64 data + 16 pad)
#define TILE_B (128*TS)               // 10240
#define STAGE_B (4*TILE_B)            // Ah,Al,Bh,Bl = 40960
#define SMEM_GEMM (3*STAGE_B)         // 122880

extern __shared__ char smem_dyn[];

__device__ __forceinline__ void cp16(uint32_t dst, const void* src) {
    asm volatile("cp.async.cg.shared.global [%0], [%1], 16;" :: "r"(dst), "l"(src));
}
__device__ __forceinline__ void cp_commit() { asm volatile("cp.async.commit_group;"); }
__device__ __forceinline__ void cp_wait1() { asm volatile("cp.async.wait_group 1;"); }

__device__ __forceinline__ void ldsm4(uint32_t* r, uint32_t addr) {
    asm volatile("ldmatrix.sync.aligned.m8n8.x4.shared.b16 {%0,%1,%2,%3}, [%4];"
                 : "=r"(r[0]), "=r"(r[1]), "=r"(r[2]), "=r"(r[3]) : "r"(addr));
}
__device__ __forceinline__ void mma16816(float* d, const uint32_t* a, const uint32_t* b) {
    asm volatile("mma.sync.aligned.m16n8k16.row.col.f32.bf16.bf16.f32 "
                 "{%0,%1,%2,%3},{%4,%5,%6,%7},{%8,%9},{%0,%1,%2,%3};"
                 : "+f"(d[0]), "+f"(d[1]), "+f"(d[2]), "+f"(d[3])
                 : "r"(a[0]), "r"(a[1]), "r"(a[2]), "r"(a[3]), "r"(b[0]), "r"(b[1]));
}

template <bool GATHER>
__device__ void mm_gemm(const __nv_bfloat16* __restrict__ Ah,
                        const __nv_bfloat16* __restrict__ Al, int lda,
                        const int* __restrict__ ridx, int M,
                        const __nv_bfloat16* __restrict__ Bh,
                        const __nv_bfloat16* __restrict__ Bl, int ldb,
                        const float* __restrict__ bias,
                        float* __restrict__ C, int ldc, int K)
{
    int m0 = blockIdx.y * 128;
    if (m0 >= M) return;
    int n0 = blockIdx.x * 128;

    int tid = threadIdx.x;             // 256
    int wid = tid >> 5, lane = tid & 31;
    char* sm = smem_dyn;
    uint32_t sBase = smem_u32(sm);

    // loader: each thread owns 2 rows (r1, r2) x one 16B column chunk q per tile
    int q  = tid & 3;                  // 16B chunk within 64B row
    int r1 = tid >> 2;                 // 0..63
    int r2 = 64 + r1;                  // 64..127
    int gm1 = m0 + r1, gm2 = m0 + r2;
    int ga1 = 0, ga2 = 0;
    if (gm1 < M) ga1 = GATHER ? ridx[gm1] : gm1;
    if (gm2 < M) ga2 = GATHER ? ridx[gm2] : gm2;
    const __nv_bfloat16* pa1h = Ah + (size_t)ga1 * lda + q * 8;
    const __nv_bfloat16* pa1l = Al + (size_t)ga1 * lda + q * 8;
    const __nv_bfloat16* pa2h = Ah + (size_t)ga2 * lda + q * 8;
    const __nv_bfloat16* pa2l = Al + (size_t)ga2 * lda + q * 8;
    const __nv_bfloat16* pb1h = Bh + (size_t)(n0 + r1) * ldb + q * 8;
    const __nv_bfloat16* pb1l = Bl + (size_t)(n0 + r1) * ldb + q * 8;
    const __nv_bfloat16* pb2h = Bh + (size_t)(n0 + r2) * ldb + q * 8;
    const __nv_bfloat16* pb2l = Bl + (size_t)(n0 + r2) * ldb + q * 8;
    uint32_t d1 = (uint32_t)(r1 * TS + q * 16);
    uint32_t d2 = (uint32_t)(r2 * TS + q * 16);

    // warp tile
    int wm = wid >> 2;                 // 0..1
    int wn = wid & 3;                  // 0..3
    uint32_t aoff = (uint32_t)((wm * 64 + (lane & 15)) * TS) + ((lane >> 4) << 4);
    uint32_t boff = (uint32_t)((wn * 32 + (lane & 7) + ((lane >> 4) & 1) * 8) * TS)
                  + (((lane >> 3) & 1) << 4);

    float acc[4][4][4];
#pragma unroll
    for (int i = 0; i < 4; i++)
#pragma unroll
        for (int j = 0; j < 4; j++)
#pragma unroll
            for (int c = 0; c < 4; c++) acc[i][j][c] = 0.f;

    int NT = K / BK;

    // stage issue
    auto issue = [&](int it) {
        uint32_t sb = sBase + (uint32_t)(it % 3) * STAGE_B;
        int k0 = it * BK;
        cp16(sb + d1,              pa1h + k0);
        cp16(sb + d2,              pa2h + k0);
        cp16(sb + TILE_B + d1,     pa1l + k0);
        cp16(sb + TILE_B + d2,     pa2l + k0);
        cp16(sb + 2 * TILE_B + d1, pb1h + k0);
        cp16(sb + 2 * TILE_B + d2, pb2h + k0);
        cp16(sb + 3 * TILE_B + d1, pb1l + k0);
        cp16(sb + 3 * TILE_B + d2, pb2l + k0);
    };

    issue(0); cp_commit();
    if (NT > 1) issue(1);
    cp_commit();

    for (int it = 0; it < NT; it++) {
        cp_wait1();
        __syncthreads();
        if (it + 2 < NT) issue(it + 2);
        cp_commit();

        uint32_t stg = (uint32_t)(it % 3) * STAGE_B;
        uint32_t Ah_s = sBase + stg + aoff;
        uint32_t Al_s = Ah_s + TILE_B;
        uint32_t Bh_s = sBase + stg + 2 * TILE_B + boff;
        uint32_t Bl_s = Bh_s + TILE_B;
#pragma unroll
        for (int k16 = 0; k16 < 2; k16++) {
            uint32_t ah[4][4], al[4][4], bh[2][4], bl[2][4];
#pragma unroll
            for (int i = 0; i < 4; i++) ldsm4(ah[i], Ah_s + i * 16 * TS + k16 * 32);
#pragma unroll
            for (int i = 0; i < 4; i++) ldsm4(al[i], Al_s + i * 16 * TS + k16 * 32);
#pragma unroll
            for (int jj = 0; jj < 2; jj++) ldsm4(bh[jj], Bh_s + jj * 16 * TS + k16 * 32);
#pragma unroll
            for (int jj = 0; jj < 2; jj++) ldsm4(bl[jj], Bl_s + jj * 16 * TS + k16 * 32);
#pragma unroll
            for (int i = 0; i < 4; i++)
#pragma unroll
                for (int j = 0; j < 4; j++) {
                    const uint32_t* bhp = &bh[j >> 1][(j & 1) * 2];
                    const uint32_t* blp = &bl[j >> 1][(j & 1) * 2];
                    mma16816(acc[i][j], ah[i], bhp);
                    mma16816(acc[i][j], al[i], bhp);
                    mma16816(acc[i][j], ah[i], blp);
                }
        }
        __syncthreads();
    }

    // epilogue
    int rbase = m0 + wm * 64 + (lane >> 2);
    int cbase = n0 + wn * 32 + (lane & 3) * 2;
#pragma unroll
    for (int i = 0; i < 4; i++) {
#pragma unroll
        for (int j = 0; j < 4; j++) {
            int r = rbase + i * 16;
            int c = cbase + j * 8;
            float b0 = bias[c], b1 = bias[c + 1];
            if (r < M) {
                float2 o = make_float2(acc[i][j][0] + b0, acc[i][j][1] + b1);
                *(float2*)(C + (size_t)r * ldc + c) = o;
            }
            if (r + 8 < M) {
                float2 o = make_float2(acc[i][j][2] + b0, acc[i][j][3] + b1);
                *(float2*)(C + (size_t)(r + 8) * ldc + c) = o;
            }
        }
    }
}

// ---------------- GEMM wrappers ----------------
__global__ void __launch_bounds__(256, 1) k_efc1(const float* __restrict__ b) {
    int e = blockIdx.z;
    int M = g_cnt[e], off = g_off[e];
    mm_gemm<true>(g_xh, g_xl, DDIM, g_ptok + off, M,
                  g_w1h + (size_t)e * 2 * FF * DDIM, g_w1l + (size_t)e * 2 * FF * DDIM, DDIM,
                  b + (size_t)e * 2 * FF,
                  g_h + (size_t)off * 2 * FF, 2 * FF, DDIM);
}

__global__ void __launch_bounds__(256, 1) k_efc2(const float* __restrict__ b) {
    int e = blockIdx.z;
    int M = g_cnt[e], off = g_off[e];
    mm_gemm<false>(g_ah + (size_t)off * FF, g_al + (size_t)off * FF, FF, nullptr, M,
                   g_w2h + (size_t)e * DDIM * FF, g_w2l + (size_t)e * DDIM * FF, FF,
                   b + (size_t)e * DDIM,
                   g_yp + (size_t)off * DDIM, DDIM, FF);
}

__global__ void __launch_bounds__(256, 1) k_sfc1(const float* __restrict__ b) {
    mm_gemm<false>(g_xh, g_xl, DDIM, nullptr, TOK, g_s1h, g_s1l, DDIM, b, g_hs, 2 * FSH, DDIM);
}

__global__ void __launch_bounds__(256, 1) k_sfc2(const float* __restrict__ b,
                                                 float* __restrict__ out) {
    mm_gemm<false>(g_ash, g_asl, FSH, nullptr, TOK, g_s2h, g_s2l, FSH, b, out, DDIM, FSH);
}

// ---------------- elementwise (geglu fused with bf16 hi/lo conversion) ----------------
__global__ void k_geglu_e(const float* __restrict__ gm) {
    int i = blockIdx.x * blockDim.x + threadIdx.x;
    const int F4 = FF / 4;
    if (i >= NPAIR * F4) return;
    int p = i / F4, f4 = i % F4;
    int e = g_pexp[p];
    const float4 xh = *(const float4*)(g_h + (size_t)p * 2 * FF + f4 * 4);
    const float4 gg = *(const float4*)(g_h + (size_t)p * 2 * FF + FF + f4 * 4);
    const float4 mu = *(const float4*)(gm + (size_t)e * FF + f4 * 4);
    float4 r;
    r.x = gelu_exact(gg.x) * xh.x * mu.x;
    r.y = gelu_exact(gg.y) * xh.y * mu.y;
    r.z = gelu_exact(gg.z) * xh.z * mu.z;
    r.w = gelu_exact(gg.w) * xh.w * mu.w;
    uint2 hv, lv;
    hilo4(r, hv, lv);
    ((uint2*)g_ah)[(size_t)p * F4 + f4] = hv;
    ((uint2*)g_al)[(size_t)p * F4 + f4] = lv;
}

__global__ void k_geglu_s(const float* __restrict__ gm) {
    int i = blockIdx.x * blockDim.x + threadIdx.x;
    const int F4 = FSH / 4;
    if (i >= TOK * F4) return;
    int t = i / F4, f4 = i % F4;
    const float4 xh = *(const float4*)(g_hs + (size_t)t * 2 * FSH + f4 * 4);
    const float4 gg = *(const float4*)(g_hs + (size_t)t * 2 * FSH + FSH + f4 * 4);
    const float4 mu = *(const float4*)(gm + f4 * 4);
    float4 r;
    r.x = gelu_exact(gg.x) * xh.x * mu.x;
    r.y = gelu_exact(gg.y) * xh.y * mu.y;
    r.z = gelu_exact(gg.z) * xh.z * mu.z;
    r.w = gelu_exact(gg.w) * xh.w * mu.w;
    uint2 hv, lv;
    hilo4(r, hv, lv);
    ((uint2*)g_ash)[(size_t)t * F4 + f4] = hv;
    ((uint2*)g_asl)[(size_t)t * F4 + f4] = lv;
}

__global__ void k_comb(float* __restrict__ out) {
    int i = blockIdx.x * blockDim.x + threadIdx.x;
    const int D4 = DDIM / 4;
    if (i >= TOK * D4) return;
    int t = i / D4, d4 = i % D4;
    float4 acc = *(float4*)(out + (size_t)t * DDIM + d4 * 4);
#pragma unroll
    for (int k = 0; k < KTOP; k++) {
        int s = g_t2s[t * KTOP + k];
        float w = g_tw[t * KTOP + k];
        const float4 v = *(const float4*)(g_yp + (size_t)s * DDIM + d4 * 4);
        acc.x += w * v.x; acc.y += w * v.y; acc.z += w * v.z; acc.w += w * v.w;
    }
    *(float4*)(out + (size_t)t * DDIM + d4 * 4) = acc;
}

// ---------------- launch ----------------
static __nv_bfloat16* devptr_bf16(const void* sym) { return nullptr; } // unused helper

extern "C" void kernel_launch(void* const* d_in, const int* in_sizes, int n_in,
                              void* d_out, int out_size) {
    const float* x       = (const float*)d_in[0];
    const float* gate_w  = (const float*)d_in[1];
    const float* fc1_w   = (const float*)d_in[2];
    const float* fc1_b   = (const float*)d_in[3];
    const float* gmult   = (const float*)d_in[4];
    const float* fc2_w   = (const float*)d_in[5];
    const float* fc2_b   = (const float*)d_in[6];
    const float* sfc1_w  = (const float*)d_in[7];
    const float* sfc1_b  = (const float*)d_in[8];
    const float* sgmult  = (const float*)d_in[9];
    const float* sfc2_w  = (const float*)d_in[10];
    const float* sfc2_b  = (const float*)d_in[11];
    float* out = (float*)d_out;

    cudaFuncSetAttribute(k_efc1, cudaFuncAttributeMaxDynamicSharedMemorySize, SMEM_GEMM);
    cudaFuncSetAttribute(k_efc2, cudaFuncAttributeMaxDynamicSharedMemorySize, SMEM_GEMM);
    cudaFuncSetAttribute(k_sfc1, cudaFuncAttributeMaxDynamicSharedMemorySize, SMEM_GEMM);
    cudaFuncSetAttribute(k_sfc2, cudaFuncAttributeMaxDynamicSharedMemorySize, SMEM_GEMM);

    // resolve device symbol addresses (host side, cached by CUDA runtime; no allocation)
    __nv_bfloat16 *xh, *xl, *w1h, *w1l, *w2h, *w2l, *s1h, *s1l, *s2h, *s2l;
    cudaGetSymbolAddress((void**)&xh,  g_xh);  cudaGetSymbolAddress((void**)&xl,  g_xl);
    cudaGetSymbolAddress((void**)&w1h, g_w1h); cudaGetSymbolAddress((void**)&w1l, g_w1l);
    cudaGetSymbolAddress((void**)&w2h, g_w2h); cudaGetSymbolAddress((void**)&w2l, g_w2l);
    cudaGetSymbolAddress((void**)&s1h, g_s1h); cudaGetSymbolAddress((void**)&s1l, g_s1l);
    cudaGetSymbolAddress((void**)&s2h, g_s2h); cudaGetSymbolAddress((void**)&s2l, g_s2l);

    // conversions
    {
        int n4 = TOK * DDIM / 4;
        k_cvt<<<(n4 + 255) / 256, 256>>>(x, xh, xl, n4);
        n4 = NEXP * 2 * FF * DDIM / 4;
        k_cvt<<<(n4 + 255) / 256, 256>>>(fc1_w, w1h, w1l, n4);
        n4 = NEXP * DDIM * FF / 4;
        k_cvt<<<(n4 + 255) / 256, 256>>>(fc2_w, w2h, w2l, n4);
        n4 = 2 * FSH * DDIM / 4;
        k_cvt<<<(n4 + 255) / 256, 256>>>(sfc1_w, s1h, s1l, n4);
        n4 = DDIM * FSH / 4;
        k_cvt<<<(n4 + 255) / 256, 256>>>(sfc2_w, s2h, s2l, n4);
    }

    zero_kernel<<<1, 32>>>();
    gate_kernel<<<TOK, 128>>>(x, gate_w);
    offsets_kernel<<<1, 1>>>();
    scatter_kernel<<<(TOK + 255) / 256, 256>>>();

    // expert fc1: N = 2F = 2048
    dim3 g1(2 * FF / 128, NPAIR / 128, NEXP);
    k_efc1<<<g1, 256, SMEM_GEMM>>>(fc1_b);
    k_geglu_e<<<(NPAIR * (FF / 4) + 255) / 256, 256>>>(gmult);

    // expert fc2: N = D = 1024
    dim3 g2(DDIM / 128, NPAIR / 128, NEXP);
    k_efc2<<<g2, 256, SMEM_GEMM>>>(fc2_b);

    // shared expert
    dim3 g3(2 * FSH / 128, TOK / 128);
    k_sfc1<<<g3, 256, SMEM_GEMM>>>(sfc1_b);
    k_geglu_s<<<(TOK * (FSH / 4) + 255) / 256, 256>>>(sgmult);
    dim3 g4(DDIM / 128, TOK / 128);
    k_sfc2<<<g4, 256, SMEM_GEMM>>>(sfc2_b, out);

    k_comb<<<(TOK * (DDIM / 4) + 255) / 256, 256>>>(out);
}

// round 5
// speedup vs baseline: 3.5008x; 1.4550x over previous
#include <cuda_runtime.h>
#include <cuda_fp16.h>
#include <math.h>
#include <stdint.h>

#define TOK   2048
#define DDIM  1024
#define NEXP  15
#define KTOP  3
#define FF    1024
#define FSH   2048
#define NPAIR (TOK*KTOP)   // 6144

// ---------------- static scratch ----------------
__device__ __align__(16) float g_h [(size_t)NPAIR * 2 * FF];      // expert fc1 out (fp32)
__device__ __align__(16) float g_yp[(size_t)NPAIR * DDIM];        // expert fc2 out
__device__ __align__(16) float g_hs[(size_t)TOK * 2 * FSH];       // shared fc1 out
// fp16 operand arrays
__device__ __align__(16) __half g_xq [(size_t)TOK * DDIM];
__device__ __align__(16) __half g_aq [(size_t)NPAIR * FF];
__device__ __align__(16) __half g_asq[(size_t)TOK * FSH];
__device__ __align__(16) __half g_w1q[(size_t)NEXP * 2 * FF * DDIM];
__device__ __align__(16) __half g_w2q[(size_t)NEXP * DDIM * FF];
__device__ __align__(16) __half g_s1q[(size_t)2 * FSH * DDIM];
__device__ __align__(16) __half g_s2q[(size_t)DDIM * FSH];

__device__ int   g_ptok[NPAIR];
__device__ int   g_pexp[NPAIR];
__device__ int   g_t2s [TOK * KTOP];
__device__ float g_tw  [TOK * KTOP];
__device__ int   g_ti  [TOK * KTOP];
__device__ int   g_cnt[NEXP], g_off[NEXP], g_cur[NEXP];

__device__ __forceinline__ float gelu_exact(float v) {
    return 0.5f * v * (1.0f + erff(v * 0.70710678118654752440f));
}
__device__ __forceinline__ uint32_t smem_u32(const void* p) {
    return (uint32_t)__cvta_generic_to_shared(p);
}
__device__ __forceinline__ uint32_t pack2h(float a, float b) {
    __half2 h = __floats2half2_rn(a, b);
    return *(uint32_t*)&h;
}

// ---------------- conversion kernel (fp32 -> fp16), grid-stride, 8 elems/thread ----------------
__global__ void k_cvt(const float* __restrict__ src, __half* __restrict__ dst, int n8) {
    int stride = gridDim.x * blockDim.x;
    for (int i = blockIdx.x * blockDim.x + threadIdx.x; i < n8; i += stride) {
        float4 v0 = ((const float4*)src)[i * 2];
        float4 v1 = ((const float4*)src)[i * 2 + 1];
        uint4 o;
        o.x = pack2h(v0.x, v0.y);
        o.y = pack2h(v0.z, v0.w);
        o.z = pack2h(v1.x, v1.y);
        o.w = pack2h(v1.z, v1.w);
        ((uint4*)dst)[i] = o;
    }
}

// ---------------- gating ----------------
__global__ void zero_kernel() {
    int i = threadIdx.x;
    if (i < NEXP) g_cnt[i] = 0;
}

__global__ void gate_kernel(const float* __restrict__ x, const float* __restrict__ gw) {
    int t = blockIdx.x;
    int tid = threadIdx.x;   // 128 threads
    float part[NEXP];
#pragma unroll
    for (int e = 0; e < NEXP; e++) part[e] = 0.f;
    const float* xr = x + (size_t)t * DDIM;
    for (int d = tid; d < DDIM; d += 128) {
        float xv = xr[d];
#pragma unroll
        for (int e = 0; e < NEXP; e++) part[e] += xv * gw[e * DDIM + d];
    }
#pragma unroll
    for (int e = 0; e < NEXP; e++)
#pragma unroll
        for (int o = 16; o > 0; o >>= 1)
            part[e] += __shfl_xor_sync(0xFFFFFFFFu, part[e], o);

    __shared__ float red[NEXP][4];
    int w = tid >> 5, l = tid & 31;
    if (l == 0)
#pragma unroll
        for (int e = 0; e < NEXP; e++) red[e][w] = part[e];
    __syncthreads();

    if (tid == 0) {
        float lg[NEXP];
#pragma unroll
        for (int e = 0; e < NEXP; e++)
            lg[e] = red[e][0] + red[e][1] + red[e][2] + red[e][3];
        float mx = lg[0];
#pragma unroll
        for (int e = 1; e < NEXP; e++) mx = fmaxf(mx, lg[e]);
        float s = 0.f, sc[NEXP];
#pragma unroll
        for (int e = 0; e < NEXP; e++) { sc[e] = expf(lg[e] - mx); s += sc[e]; }
        float inv = 1.f / s;
#pragma unroll
        for (int e = 0; e < NEXP; e++) sc[e] *= inv;

        int   idx[KTOP];
        float wv [KTOP];
        float wsum = 0.f;
#pragma unroll
        for (int k = 0; k < KTOP; k++) {
            int   bi = 0;
            float bv = -1.f;
#pragma unroll
            for (int e = 0; e < NEXP; e++)
                if (sc[e] > bv) { bv = sc[e]; bi = e; }
            idx[k] = bi; wv[k] = bv; wsum += bv;
            sc[bi] = -2.f;
        }
        float winv = 1.f / (wsum + 1e-20f);
#pragma unroll
        for (int k = 0; k < KTOP; k++) {
            g_ti[t * KTOP + k] = idx[k];
            g_tw[t * KTOP + k] = wv[k] * winv;
            atomicAdd(&g_cnt[idx[k]], 1);
        }
    }
}

__global__ void offsets_kernel() {
    if (threadIdx.x == 0) {
        int cum = 0;
        for (int e = 0; e < NEXP; e++) {
            g_off[e] = cum;
            cum += g_cnt[e];
            g_cur[e] = 0;
        }
    }
}

__global__ void scatter_kernel() {
    int t = blockIdx.x * blockDim.x + threadIdx.x;
    if (t >= TOK) return;
#pragma unroll
    for (int k = 0; k < KTOP; k++) {
        int e = g_ti[t * KTOP + k];
        int pos = atomicAdd(&g_cur[e], 1);
        int s = g_off[e] + pos;
        g_ptok[s] = t;
        g_pexp[s] = e;
        g_t2s[t * KTOP + k] = s;
    }
}

// ---------------- fp16 mma.sync GEMM with cp.async pipeline ----------------
// C(MxN) = A(MxK) * B(NxK)^T + bias; operands fp16, accum/out fp32.
// CTA 128x128, 8 warps (2x4) -> 64x32 warp tiles, K-chunk 64, 3-stage ring, 1 sync/stage.
#define BK  64
#define TS  144                       // row stride bytes (128 data + 16 pad)
#define TILE_B (128*TS)               // 18432
#define STAGE_B (2*TILE_B)            // A,B = 36864
#define SMEM_GEMM (3*STAGE_B)         // 110592

extern __shared__ char smem_dyn[];

__device__ __forceinline__ void cp16(uint32_t dst, const void* src) {
    asm volatile("cp.async.cg.shared.global [%0], [%1], 16;" :: "r"(dst), "l"(src));
}
__device__ __forceinline__ void cp_commit() { asm volatile("cp.async.commit_group;"); }
__device__ __forceinline__ void cp_wait1() { asm volatile("cp.async.wait_group 1;"); }

__device__ __forceinline__ void ldsm4(uint32_t* r, uint32_t addr) {
    asm volatile("ldmatrix.sync.aligned.m8n8.x4.shared.b16 {%0,%1,%2,%3}, [%4];"
                 : "=r"(r[0]), "=r"(r[1]), "=r"(r[2]), "=r"(r[3]) : "r"(addr));
}
__device__ __forceinline__ void mma16816(float* d, const uint32_t* a, const uint32_t* b) {
    asm volatile("mma.sync.aligned.m16n8k16.row.col.f32.f16.f16.f32 "
                 "{%0,%1,%2,%3},{%4,%5,%6,%7},{%8,%9},{%0,%1,%2,%3};"
                 : "+f"(d[0]), "+f"(d[1]), "+f"(d[2]), "+f"(d[3])
                 : "r"(a[0]), "r"(a[1]), "r"(a[2]), "r"(a[3]), "r"(b[0]), "r"(b[1]));
}

template <bool GATHER>
__device__ void mm_gemm(const __half* __restrict__ A, int lda,
                        const int* __restrict__ ridx, int M,
                        const __half* __restrict__ B, int ldb,
                        const float* __restrict__ bias,
                        float* __restrict__ C, int ldc, int K)
{
    int m0 = blockIdx.y * 128;
    if (m0 >= M) return;
    int n0 = blockIdx.x * 128;

    int tid = threadIdx.x;             // 256
    int wid = tid >> 5, lane = tid & 31;
    char* sm = smem_dyn;
    uint32_t sBase = smem_u32(sm);

    // loader: each thread owns one row x four 16B chunks per tile
    int lrow = tid >> 1;               // 0..127
    int cb   = (tid & 1) * 4;          // chunk base (of 8 chunks per 128B row)
    int gm = m0 + lrow;
    int ga = 0;
    if (gm < M) ga = GATHER ? ridx[gm] : gm;
    const __half* pa = A + (size_t)ga * lda + cb * 8;
    const __half* pb = B + (size_t)(n0 + lrow) * ldb + cb * 8;
    uint32_t dsto = (uint32_t)(lrow * TS + cb * 16);

    // warp tile
    int wm = wid >> 2;                 // 0..1 -> m off wm*64
    int wn = wid & 3;                  // 0..3 -> n off wn*32
    uint32_t aoff = (uint32_t)((wm * 64 + (lane & 15)) * TS) + ((lane >> 4) << 4);
    uint32_t boff = (uint32_t)((wn * 32 + (lane & 7) + ((lane >> 4) & 1) * 8) * TS)
                  + (((lane >> 3) & 1) << 4);

    float acc[4][4][4];
#pragma unroll
    for (int i = 0; i < 4; i++)
#pragma unroll
        for (int j = 0; j < 4; j++)
#pragma unroll
            for (int c = 0; c < 4; c++) acc[i][j][c] = 0.f;

    int NT = K / BK;

    auto issue = [&](int it) {
        uint32_t sb = sBase + (uint32_t)(it % 3) * STAGE_B;
        int k0 = it * BK;
#pragma unroll
        for (int j = 0; j < 4; j++) {
            cp16(sb + dsto + j * 16,          pa + k0 + j * 8);
            cp16(sb + TILE_B + dsto + j * 16, pb + k0 + j * 8);
        }
    };

    issue(0); cp_commit();
    issue(1); cp_commit();

    for (int it = 0; it < NT; it++) {
        cp_wait1();
        __syncthreads();
        if (it + 2 < NT) { issue(it + 2); }
        cp_commit();

        uint32_t stg = sBase + (uint32_t)(it % 3) * STAGE_B;
        uint32_t As = stg + aoff;
        uint32_t Bs = stg + TILE_B + boff;
#pragma unroll
        for (int k16 = 0; k16 < 4; k16++) {
            uint32_t a[4][4], b[2][4];
#pragma unroll
            for (int jj = 0; jj < 2; jj++) ldsm4(b[jj], Bs + jj * 16 * TS + k16 * 32);
#pragma unroll
            for (int i = 0; i < 4; i++) {
                ldsm4(a[i], As + i * 16 * TS + k16 * 32);
#pragma unroll
                for (int j = 0; j < 4; j++)
                    mma16816(acc[i][j], a[i], &b[j >> 1][(j & 1) * 2]);
            }
        }
    }

    // epilogue
    int rbase = m0 + wm * 64 + (lane >> 2);
    int cbase = n0 + wn * 32 + (lane & 3) * 2;
#pragma unroll
    for (int i = 0; i < 4; i++) {
#pragma unroll
        for (int j = 0; j < 4; j++) {
            int r = rbase + i * 16;
            int c = cbase + j * 8;
            float b0 = bias[c], b1 = bias[c + 1];
            if (r < M) {
                float2 o = make_float2(acc[i][j][0] + b0, acc[i][j][1] + b1);
                *(float2*)(C + (size_t)r * ldc + c) = o;
            }
            if (r + 8 < M) {
                float2 o = make_float2(acc[i][j][2] + b0, acc[i][j][3] + b1);
                *(float2*)(C + (size_t)(r + 8) * ldc + c) = o;
            }
        }
    }
}

// ---------------- GEMM wrappers ----------------
__global__ void __launch_bounds__(256, 1) k_efc1(const float* __restrict__ b) {
    int e = blockIdx.z;
    int M = g_cnt[e], off = g_off[e];
    mm_gemm<true>(g_xq, DDIM, g_ptok + off, M,
                  g_w1q + (size_t)e * 2 * FF * DDIM, DDIM,
                  b + (size_t)e * 2 * FF,
                  g_h + (size_t)off * 2 * FF, 2 * FF, DDIM);
}

__global__ void __launch_bounds__(256, 1) k_efc2(const float* __restrict__ b) {
    int e = blockIdx.z;
    int M = g_cnt[e], off = g_off[e];
    mm_gemm<false>(g_aq + (size_t)off * FF, FF, nullptr, M,
                   g_w2q + (size_t)e * DDIM * FF, FF,
                   b + (size_t)e * DDIM,
                   g_yp + (size_t)off * DDIM, DDIM, FF);
}

__global__ void __launch_bounds__(256, 1) k_sfc1(const float* __restrict__ b) {
    mm_gemm<false>(g_xq, DDIM, nullptr, TOK, g_s1q, DDIM, b, g_hs, 2 * FSH, DDIM);
}

__global__ void __launch_bounds__(256, 1) k_sfc2(const float* __restrict__ b,
                                                 float* __restrict__ out) {
    mm_gemm<false>(g_asq, FSH, nullptr, TOK, g_s2q, FSH, b, out, DDIM, FSH);
}

// ---------------- elementwise (geglu fused with fp16 conversion) ----------------
__global__ void k_geglu_e(const float* __restrict__ gm) {
    int i = blockIdx.x * blockDim.x + threadIdx.x;
    const int F4 = FF / 4;
    if (i >= NPAIR * F4) return;
    int p = i / F4, f4 = i % F4;
    int e = g_pexp[p];
    const float4 xh = *(const float4*)(g_h + (size_t)p * 2 * FF + f4 * 4);
    const float4 gg = *(const float4*)(g_h + (size_t)p * 2 * FF + FF + f4 * 4);
    const float4 mu = *(const float4*)(gm + (size_t)e * FF + f4 * 4);
    float4 r;
    r.x = gelu_exact(gg.x) * xh.x * mu.x;
    r.y = gelu_exact(gg.y) * xh.y * mu.y;
    r.z = gelu_exact(gg.z) * xh.z * mu.z;
    r.w = gelu_exact(gg.w) * xh.w * mu.w;
    uint2 o;
    o.x = pack2h(r.x, r.y);
    o.y = pack2h(r.z, r.w);
    ((uint2*)g_aq)[(size_t)p * F4 + f4] = o;
}

__global__ void k_geglu_s(const float* __restrict__ gm) {
    int i = blockIdx.x * blockDim.x + threadIdx.x;
    const int F4 = FSH / 4;
    if (i >= TOK * F4) return;
    int t = i / F4, f4 = i % F4;
    const float4 xh = *(const float4*)(g_hs + (size_t)t * 2 * FSH + f4 * 4);
    const float4 gg = *(const float4*)(g_hs + (size_t)t * 2 * FSH + FSH + f4 * 4);
    const float4 mu = *(const float4*)(gm + f4 * 4);
    float4 r;
    r.x = gelu_exact(gg.x) * xh.x * mu.x;
    r.y = gelu_exact(gg.y) * xh.y * mu.y;
    r.z = gelu_exact(gg.z) * xh.z * mu.z;
    r.w = gelu_exact(gg.w) * xh.w * mu.w;
    uint2 o;
    o.x = pack2h(r.x, r.y);
    o.y = pack2h(r.z, r.w);
    ((uint2*)g_asq)[(size_t)t * F4 + f4] = o;
}

__global__ void k_comb(float* __restrict__ out) {
    int i = blockIdx.x * blockDim.x + threadIdx.x;
    const int D4 = DDIM / 4;
    if (i >= TOK * D4) return;
    int t = i / D4, d4 = i % D4;
    float4 acc = *(float4*)(out + (size_t)t * DDIM + d4 * 4);
#pragma unroll
    for (int k = 0; k < KTOP; k++) {
        int s = g_t2s[t * KTOP + k];
        float w = g_tw[t * KTOP + k];
        const float4 v = *(const float4*)(g_yp + (size_t)s * DDIM + d4 * 4);
        acc.x += w * v.x; acc.y += w * v.y; acc.z += w * v.z; acc.w += w * v.w;
    }
    *(float4*)(out + (size_t)t * DDIM + d4 * 4) = acc;
}

// ---------------- launch ----------------
extern "C" void kernel_launch(void* const* d_in, const int* in_sizes, int n_in,
                              void* d_out, int out_size) {
    const float* x       = (const float*)d_in[0];
    const float* gate_w  = (const float*)d_in[1];
    const float* fc1_w   = (const float*)d_in[2];
    const float* fc1_b   = (const float*)d_in[3];
    const float* gmult   = (const float*)d_in[4];
    const float* fc2_w   = (const float*)d_in[5];
    const float* fc2_b   = (const float*)d_in[6];
    const float* sfc1_w  = (const float*)d_in[7];
    const float* sfc1_b  = (const float*)d_in[8];
    const float* sgmult  = (const float*)d_in[9];
    const float* sfc2_w  = (const float*)d_in[10];
    const float* sfc2_b  = (const float*)d_in[11];
    float* out = (float*)d_out;

    cudaFuncSetAttribute(k_efc1, cudaFuncAttributeMaxDynamicSharedMemorySize, SMEM_GEMM);
    cudaFuncSetAttribute(k_efc2, cudaFuncAttributeMaxDynamicSharedMemorySize, SMEM_GEMM);
    cudaFuncSetAttribute(k_sfc1, cudaFuncAttributeMaxDynamicSharedMemorySize, SMEM_GEMM);
    cudaFuncSetAttribute(k_sfc2, cudaFuncAttributeMaxDynamicSharedMemorySize, SMEM_GEMM);

    __half *xq, *w1q, *w2q, *s1q, *s2q;
    cudaGetSymbolAddress((void**)&xq,  g_xq);
    cudaGetSymbolAddress((void**)&w1q, g_w1q);
    cudaGetSymbolAddress((void**)&w2q, g_w2q);
    cudaGetSymbolAddress((void**)&s1q, g_s1q);
    cudaGetSymbolAddress((void**)&s2q, g_s2q);

    // conversions (grid-stride, 8 elems/thread/iter)
    {
        int n8 = TOK * DDIM / 8;
        k_cvt<<<592, 256>>>(x, xq, n8);
        n8 = NEXP * 2 * FF * DDIM / 8;
        k_cvt<<<2368, 256>>>(fc1_w, w1q, n8);
        n8 = NEXP * DDIM * FF / 8;
        k_cvt<<<2368, 256>>>(fc2_w, w2q, n8);
        n8 = 2 * FSH * DDIM / 8;
        k_cvt<<<1184, 256>>>(sfc1_w, s1q, n8);
        n8 = DDIM * FSH / 8;
        k_cvt<<<1184, 256>>>(sfc2_w, s2q, n8);
    }

    zero_kernel<<<1, 32>>>();
    gate_kernel<<<TOK, 128>>>(x, gate_w);
    offsets_kernel<<<1, 1>>>();
    scatter_kernel<<<(TOK + 255) / 256, 256>>>();

    // expert fc1: N = 2F = 2048
    dim3 g1(2 * FF / 128, NPAIR / 128, NEXP);
    k_efc1<<<g1, 256, SMEM_GEMM>>>(fc1_b);
    k_geglu_e<<<(NPAIR * (FF / 4) + 255) / 256, 256>>>(gmult);

    // expert fc2: N = D = 1024
    dim3 g2(DDIM / 128, NPAIR / 128, NEXP);
    k_efc2<<<g2, 256, SMEM_GEMM>>>(fc2_b);

    // shared expert
    dim3 g3(2 * FSH / 128, TOK / 128);
    k_sfc1<<<g3, 256, SMEM_GEMM>>>(sfc1_b);
    k_geglu_s<<<(TOK * (FSH / 4) + 255) / 256, 256>>>(sgmult);
    dim3 g4(DDIM / 128, TOK / 128);
    k_sfc2<<<g4, 256, SMEM_GEMM>>>(sfc2_b, out);

    k_comb<<<(TOK * (DDIM / 4) + 255) / 256, 256>>>(out);
}

// round 6
// speedup vs baseline: 4.1006x; 1.1713x over previous
#include <cuda_runtime.h>
#include <cuda_fp16.h>
#include <math.h>
#include <stdint.h>

#define TOK   2048
#define DDIM  1024
#define NEXP  15
#define KTOP  3
#define FF    1024
#define FSH   2048
#define NPAIR (TOK*KTOP)   // 6144

// ---------------- static scratch ----------------
__device__ __align__(16) float g_h [(size_t)NPAIR * 2 * FF];      // expert fc1 out (fp32)
__device__ __align__(16) float g_yp[(size_t)NPAIR * DDIM];        // expert fc2 out
__device__ __align__(16) float g_hs[(size_t)TOK * 2 * FSH];       // shared fc1 out
// fp16 operand arrays
__device__ __align__(16) __half g_xq [(size_t)TOK * DDIM];
__device__ __align__(16) __half g_aq [(size_t)NPAIR * FF];
__device__ __align__(16) __half g_asq[(size_t)TOK * FSH];
__device__ __align__(16) __half g_w1q[(size_t)NEXP * 2 * FF * DDIM];
__device__ __align__(16) __half g_w2q[(size_t)NEXP * DDIM * FF];
__device__ __align__(16) __half g_s1q[(size_t)2 * FSH * DDIM];
__device__ __align__(16) __half g_s2q[(size_t)DDIM * FSH];

__device__ int   g_ptok[NPAIR];
__device__ int   g_pexp[NPAIR];
__device__ int   g_t2s [TOK * KTOP];
__device__ float g_tw  [TOK * KTOP];
__device__ int   g_ti  [TOK * KTOP];
__device__ int   g_cnt[NEXP], g_off[NEXP];

__device__ __forceinline__ float gelu_exact(float v) {
    return 0.5f * v * (1.0f + erff(v * 0.70710678118654752440f));
}
__device__ __forceinline__ uint32_t smem_u32(const void* p) {
    return (uint32_t)__cvta_generic_to_shared(p);
}
__device__ __forceinline__ uint32_t pack2h(float a, float b) {
    __half2 h = __floats2half2_rn(a, b);
    return *(uint32_t*)&h;
}

// ---------------- conversion kernel (fp32 -> fp16), one-shot, 8 elems/thread ----------------
__global__ void k_cvt(const float* __restrict__ src, __half* __restrict__ dst, int n8) {
    int i = blockIdx.x * blockDim.x + threadIdx.x;
    if (i >= n8) return;
    float4 v0 = ((const float4*)src)[i * 2];
    float4 v1 = ((const float4*)src)[i * 2 + 1];
    uint4 o;
    o.x = pack2h(v0.x, v0.y);
    o.y = pack2h(v0.z, v0.w);
    o.z = pack2h(v1.x, v1.y);
    o.w = pack2h(v1.z, v1.w);
    ((uint4*)dst)[i] = o;
}

// ---------------- gating ----------------
__global__ void zero_kernel() {
    int i = threadIdx.x;
    if (i < NEXP) g_cnt[i] = 0;
}

__global__ void gate_kernel(const float* __restrict__ x, const float* __restrict__ gw) {
    int t = blockIdx.x;
    int tid = threadIdx.x;   // 128 threads
    float part[NEXP];
#pragma unroll
    for (int e = 0; e < NEXP; e++) part[e] = 0.f;
    const float* xr = x + (size_t)t * DDIM;
    for (int d = tid; d < DDIM; d += 128) {
        float xv = xr[d];
#pragma unroll
        for (int e = 0; e < NEXP; e++) part[e] += xv * gw[e * DDIM + d];
    }
#pragma unroll
    for (int e = 0; e < NEXP; e++)
#pragma unroll
        for (int o = 16; o > 0; o >>= 1)
            part[e] += __shfl_xor_sync(0xFFFFFFFFu, part[e], o);

    __shared__ float red[NEXP][4];
    int w = tid >> 5, l = tid & 31;
    if (l == 0)
#pragma unroll
        for (int e = 0; e < NEXP; e++) red[e][w] = part[e];
    __syncthreads();

    if (tid == 0) {
        float lg[NEXP];
#pragma unroll
        for (int e = 0; e < NEXP; e++)
            lg[e] = red[e][0] + red[e][1] + red[e][2] + red[e][3];
        float mx = lg[0];
#pragma unroll
        for (int e = 1; e < NEXP; e++) mx = fmaxf(mx, lg[e]);
        float s = 0.f, sc[NEXP];
#pragma unroll
        for (int e = 0; e < NEXP; e++) { sc[e] = expf(lg[e] - mx); s += sc[e]; }
        float inv = 1.f / s;
#pragma unroll
        for (int e = 0; e < NEXP; e++) sc[e] *= inv;

        int   idx[KTOP];
        float wv [KTOP];
        float wsum = 0.f;
#pragma unroll
        for (int k = 0; k < KTOP; k++) {
            int   bi = 0;
            float bv = -1.f;
#pragma unroll
            for (int e = 0; e < NEXP; e++)
                if (sc[e] > bv) { bv = sc[e]; bi = e; }
            idx[k] = bi; wv[k] = bv; wsum += bv;
            sc[bi] = -2.f;
        }
        float winv = 1.f / (wsum + 1e-20f);
#pragma unroll
        for (int k = 0; k < KTOP; k++) {
            g_ti[t * KTOP + k] = idx[k];
            g_tw[t * KTOP + k] = wv[k] * winv;
            atomicAdd(&g_cnt[idx[k]], 1);
        }
    }
}

// offsets + scatter in one single-block kernel
__global__ void route_kernel() {
    __shared__ int cur[NEXP];
    int tid = threadIdx.x;           // 1024
    if (tid == 0) {
        int cum = 0;
        for (int e = 0; e < NEXP; e++) {
            g_off[e] = cum;
            cur[e] = cum;
            cum += g_cnt[e];
        }
    }
    __syncthreads();
#pragma unroll
    for (int rep = 0; rep < 2; rep++) {
        int t = tid + rep * 1024;
        if (t < TOK) {
#pragma unroll
            for (int k = 0; k < KTOP; k++) {
                int e = g_ti[t * KTOP + k];
                int s = atomicAdd(&cur[e], 1);
                g_ptok[s] = t;
                g_pexp[s] = e;
                g_t2s[t * KTOP + k] = s;
            }
        }
    }
}

// ---------------- fp16 mma.sync GEMM with cp.async pipeline ----------------
// C(MxN) = A(MxK) * B(NxK)^T + bias; operands fp16, accum/out fp32.
// CTA 128x128, 8 warps (2x4) -> 64x32 warp tiles, K-chunk 32, 3-stage ring, 2 CTAs/SM.
#define BK  32
#define TS  80                        // row stride bytes (64 data + 16 pad)
#define TILE_B (128*TS)               // 10240
#define STAGE_B (2*TILE_B)            // A,B = 20480
#define SMEM_GEMM (3*STAGE_B)         // 61440

extern __shared__ char smem_dyn[];

__device__ __forceinline__ void cp16(uint32_t dst, const void* src) {
    asm volatile("cp.async.cg.shared.global [%0], [%1], 16;" :: "r"(dst), "l"(src));
}
__device__ __forceinline__ void cp_commit() { asm volatile("cp.async.commit_group;"); }
__device__ __forceinline__ void cp_wait1() { asm volatile("cp.async.wait_group 1;"); }

__device__ __forceinline__ void ldsm4(uint32_t* r, uint32_t addr) {
    asm volatile("ldmatrix.sync.aligned.m8n8.x4.shared.b16 {%0,%1,%2,%3}, [%4];"
                 : "=r"(r[0]), "=r"(r[1]), "=r"(r[2]), "=r"(r[3]) : "r"(addr));
}
__device__ __forceinline__ void mma16816(float* d, const uint32_t* a, const uint32_t* b) {
    asm volatile("mma.sync.aligned.m16n8k16.row.col.f32.f16.f16.f32 "
                 "{%0,%1,%2,%3},{%4,%5,%6,%7},{%8,%9},{%0,%1,%2,%3};"
                 : "+f"(d[0]), "+f"(d[1]), "+f"(d[2]), "+f"(d[3])
                 : "r"(a[0]), "r"(a[1]), "r"(a[2]), "r"(a[3]), "r"(b[0]), "r"(b[1]));
}

template <bool GATHER>
__device__ void mm_gemm(const __half* __restrict__ A, int lda,
                        const int* __restrict__ ridx, int M,
                        const __half* __restrict__ B, int ldb,
                        const float* __restrict__ bias,
                        float* __restrict__ C, int ldc, int K)
{
    int m0 = blockIdx.x * 128;       // M on x (fast) -> consecutive CTAs share B tile in L2
    if (m0 >= M) return;
    int n0 = blockIdx.y * 128;

    int tid = threadIdx.x;             // 256
    int wid = tid >> 5, lane = tid & 31;
    char* sm = smem_dyn;
    uint32_t sBase = smem_u32(sm);

    // loader: each thread owns one row x two 16B chunks (of 4 per 64B row) per tile
    int lrow = tid >> 1;               // 0..127
    int cb   = (tid & 1) * 2;          // chunk base
    int gm = m0 + lrow;
    int ga = 0;
    if (gm < M) ga = GATHER ? ridx[gm] : gm;
    const __half* pa = A + (size_t)ga * lda + cb * 8;
    const __half* pb = B + (size_t)(n0 + lrow) * ldb + cb * 8;
    uint32_t dsto = (uint32_t)(lrow * TS + cb * 16);

    // warp tile
    int wm = wid >> 2;                 // 0..1 -> m off wm*64
    int wn = wid & 3;                  // 0..3 -> n off wn*32
    uint32_t aoff = (uint32_t)((wm * 64 + (lane & 15)) * TS) + ((lane >> 4) << 4);
    uint32_t boff = (uint32_t)((wn * 32 + (lane & 7) + ((lane >> 4) & 1) * 8) * TS)
                  + (((lane >> 3) & 1) << 4);

    float acc[4][4][4];
#pragma unroll
    for (int i = 0; i < 4; i++)
#pragma unroll
        for (int j = 0; j < 4; j++)
#pragma unroll
            for (int c = 0; c < 4; c++) acc[i][j][c] = 0.f;

    int NT = K / BK;

    auto issue = [&](int it) {
        uint32_t sb = sBase + (uint32_t)(it % 3) * STAGE_B;
        int k0 = it * BK;
#pragma unroll
        for (int j = 0; j < 2; j++) {
            cp16(sb + dsto + j * 16,          pa + k0 + j * 8);
            cp16(sb + TILE_B + dsto + j * 16, pb + k0 + j * 8);
        }
    };

    issue(0); cp_commit();
    issue(1); cp_commit();

    for (int it = 0; it < NT; it++) {
        cp_wait1();
        __syncthreads();
        if (it + 2 < NT) { issue(it + 2); }
        cp_commit();

        uint32_t stg = sBase + (uint32_t)(it % 3) * STAGE_B;
        uint32_t As = stg + aoff;
        uint32_t Bs = stg + TILE_B + boff;
#pragma unroll
        for (int k16 = 0; k16 < 2; k16++) {
            uint32_t a[4][4], b[2][4];
#pragma unroll
            for (int jj = 0; jj < 2; jj++) ldsm4(b[jj], Bs + jj * 16 * TS + k16 * 32);
#pragma unroll
            for (int i = 0; i < 4; i++) {
                ldsm4(a[i], As + i * 16 * TS + k16 * 32);
#pragma unroll
                for (int j = 0; j < 4; j++)
                    mma16816(acc[i][j], a[i], &b[j >> 1][(j & 1) * 2]);
            }
        }
    }

    // epilogue
    int rbase = m0 + wm * 64 + (lane >> 2);
    int cbase = n0 + wn * 32 + (lane & 3) * 2;
#pragma unroll
    for (int i = 0; i < 4; i++) {
#pragma unroll
        for (int j = 0; j < 4; j++) {
            int r = rbase + i * 16;
            int c = cbase + j * 8;
            float b0 = bias[c], b1 = bias[c + 1];
            if (r < M) {
                float2 o = make_float2(acc[i][j][0] + b0, acc[i][j][1] + b1);
                *(float2*)(C + (size_t)r * ldc + c) = o;
            }
            if (r + 8 < M) {
                float2 o = make_float2(acc[i][j][2] + b0, acc[i][j][3] + b1);
                *(float2*)(C + (size_t)(r + 8) * ldc + c) = o;
            }
        }
    }
}

// ---------------- GEMM wrappers ----------------
__global__ void __launch_bounds__(256, 2) k_efc1(const float* __restrict__ b) {
    int e = blockIdx.z;
    int M = g_cnt[e], off = g_off[e];
    mm_gemm<true>(g_xq, DDIM, g_ptok + off, M,
                  g_w1q + (size_t)e * 2 * FF * DDIM, DDIM,
                  b + (size_t)e * 2 * FF,
                  g_h + (size_t)off * 2 * FF, 2 * FF, DDIM);
}

__global__ void __launch_bounds__(256, 2) k_efc2(const float* __restrict__ b) {
    int e = blockIdx.z;
    int M = g_cnt[e], off = g_off[e];
    mm_gemm<false>(g_aq + (size_t)off * FF, FF, nullptr, M,
                   g_w2q + (size_t)e * DDIM * FF, FF,
                   b + (size_t)e * DDIM,
                   g_yp + (size_t)off * DDIM, DDIM, FF);
}

__global__ void __launch_bounds__(256, 2) k_sfc1(const float* __restrict__ b) {
    mm_gemm<false>(g_xq, DDIM, nullptr, TOK, g_s1q, DDIM, b, g_hs, 2 * FSH, DDIM);
}

__global__ void __launch_bounds__(256, 2) k_sfc2(const float* __restrict__ b,
                                                 float* __restrict__ out) {
    mm_gemm<false>(g_asq, FSH, nullptr, TOK, g_s2q, FSH, b, out, DDIM, FSH);
}

// ---------------- elementwise (geglu fused with fp16 conversion) ----------------
__global__ void k_geglu_e(const float* __restrict__ gm) {
    int i = blockIdx.x * blockDim.x + threadIdx.x;
    const int F4 = FF / 4;
    if (i >= NPAIR * F4) return;
    int p = i / F4, f4 = i % F4;
    int e = g_pexp[p];
    const float4 xh = *(const float4*)(g_h + (size_t)p * 2 * FF + f4 * 4);
    const float4 gg = *(const float4*)(g_h + (size_t)p * 2 * FF + FF + f4 * 4);
    const float4 mu = *(const float4*)(gm + (size_t)e * FF + f4 * 4);
    float4 r;
    r.x = gelu_exact(gg.x) * xh.x * mu.x;
    r.y = gelu_exact(gg.y) * xh.y * mu.y;
    r.z = gelu_exact(gg.z) * xh.z * mu.z;
    r.w = gelu_exact(gg.w) * xh.w * mu.w;
    uint2 o;
    o.x = pack2h(r.x, r.y);
    o.y = pack2h(r.z, r.w);
    ((uint2*)g_aq)[(size_t)p * F4 + f4] = o;
}

__global__ void k_geglu_s(const float* __restrict__ gm) {
    int i = blockIdx.x * blockDim.x + threadIdx.x;
    const int F4 = FSH / 4;
    if (i >= TOK * F4) return;
    int t = i / F4, f4 = i % F4;
    const float4 xh = *(const float4*)(g_hs + (size_t)t * 2 * FSH + f4 * 4);
    const float4 gg = *(const float4*)(g_hs + (size_t)t * 2 * FSH + FSH + f4 * 4);
    const float4 mu = *(const float4*)(gm + f4 * 4);
    float4 r;
    r.x = gelu_exact(gg.x) * xh.x * mu.x;
    r.y = gelu_exact(gg.y) * xh.y * mu.y;
    r.z = gelu_exact(gg.z) * xh.z * mu.z;
    r.w = gelu_exact(gg.w) * xh.w * mu.w;
    uint2 o;
    o.x = pack2h(r.x, r.y);
    o.y = pack2h(r.z, r.w);
    ((uint2*)g_asq)[(size_t)t * F4 + f4] = o;
}

__global__ void k_comb(float* __restrict__ out) {
    int i = blockIdx.x * blockDim.x + threadIdx.x;
    const int D4 = DDIM / 4;
    if (i >= TOK * D4) return;
    int t = i / D4, d4 = i % D4;
    float4 acc = *(float4*)(out + (size_t)t * DDIM + d4 * 4);
#pragma unroll
    for (int k = 0; k < KTOP; k++) {
        int s = g_t2s[t * KTOP + k];
        float w = g_tw[t * KTOP + k];
        const float4 v = *(const float4*)(g_yp + (size_t)s * DDIM + d4 * 4);
        acc.x += w * v.x; acc.y += w * v.y; acc.z += w * v.z; acc.w += w * v.w;
    }
    *(float4*)(out + (size_t)t * DDIM + d4 * 4) = acc;
}

// ---------------- launch ----------------
extern "C" void kernel_launch(void* const* d_in, const int* in_sizes, int n_in,
                              void* d_out, int out_size) {
    const float* x       = (const float*)d_in[0];
    const float* gate_w  = (const float*)d_in[1];
    const float* fc1_w   = (const float*)d_in[2];
    const float* fc1_b   = (const float*)d_in[3];
    const float* gmult   = (const float*)d_in[4];
    const float* fc2_w   = (const float*)d_in[5];
    const float* fc2_b   = (const float*)d_in[6];
    const float* sfc1_w  = (const float*)d_in[7];
    const float* sfc1_b  = (const float*)d_in[8];
    const float* sgmult  = (const float*)d_in[9];
    const float* sfc2_w  = (const float*)d_in[10];
    const float* sfc2_b  = (const float*)d_in[11];
    float* out = (float*)d_out;

    cudaFuncSetAttribute(k_efc1, cudaFuncAttributeMaxDynamicSharedMemorySize, SMEM_GEMM);
    cudaFuncSetAttribute(k_efc2, cudaFuncAttributeMaxDynamicSharedMemorySize, SMEM_GEMM);
    cudaFuncSetAttribute(k_sfc1, cudaFuncAttributeMaxDynamicSharedMemorySize, SMEM_GEMM);
    cudaFuncSetAttribute(k_sfc2, cudaFuncAttributeMaxDynamicSharedMemorySize, SMEM_GEMM);

    __half *xq, *w1q, *w2q, *s1q, *s2q;
    cudaGetSymbolAddress((void**)&xq,  g_xq);
    cudaGetSymbolAddress((void**)&w1q, g_w1q);
    cudaGetSymbolAddress((void**)&w2q, g_w2q);
    cudaGetSymbolAddress((void**)&s1q, g_s1q);
    cudaGetSymbolAddress((void**)&s2q, g_s2q);

    // conversions (one-shot, 8 elems/thread)
    {
        int n8 = TOK * DDIM / 8;
        k_cvt<<<(n8 + 255) / 256, 256>>>(x, xq, n8);
        n8 = NEXP * 2 * FF * DDIM / 8;
        k_cvt<<<(n8 + 255) / 256, 256>>>(fc1_w, w1q, n8);
        n8 = NEXP * DDIM * FF / 8;
        k_cvt<<<(n8 + 255) / 256, 256>>>(fc2_w, w2q, n8);
        n8 = 2 * FSH * DDIM / 8;
        k_cvt<<<(n8 + 255) / 256, 256>>>(sfc1_w, s1q, n8);
        n8 = DDIM * FSH / 8;
        k_cvt<<<(n8 + 255) / 256, 256>>>(sfc2_w, s2q, n8);
    }

    zero_kernel<<<1, 32>>>();
    gate_kernel<<<TOK, 128>>>(x, gate_w);
    route_kernel<<<1, 1024>>>();

    // expert fc1: N = 2F = 2048 (x = M-tiles, y = N-tiles)
    dim3 g1(NPAIR / 128, 2 * FF / 128, NEXP);
    k_efc1<<<g1, 256, SMEM_GEMM>>>(fc1_b);
    k_geglu_e<<<(NPAIR * (FF / 4) + 255) / 256, 256>>>(gmult);

    // expert fc2: N = D = 1024
    dim3 g2(NPAIR / 128, DDIM / 128, NEXP);
    k_efc2<<<g2, 256, SMEM_GEMM>>>(fc2_b);

    // shared expert
    dim3 g3(TOK / 128, 2 * FSH / 128);
    k_sfc1<<<g3, 256, SMEM_GEMM>>>(sfc1_b);
    k_geglu_s<<<(TOK * (FSH / 4) + 255) / 256, 256>>>(sgmult);
    dim3 g4(TOK / 128, DDIM / 128);
    k_sfc2<<<g4, 256, SMEM_GEMM>>>(sfc2_b, out);

    k_comb<<<(TOK * (DDIM / 4) + 255) / 256, 256>>>(out);
}